// round 1
// baseline (speedup 1.0000x reference)
#include <cuda_runtime.h>

#define D 2048
#define NROWS 16384
#define RPB 4
#define NBLOCKS (NROWS / RPB)
#define GRP_OFF 0
#define HEX_OFF (NROWS * 3)
#define LB_OFF (HEX_OFF + NROWS * 64)

#define PARTS_STRIDE 53
#define SMEM_FLOATS (256 * PARTS_STRIDE + 208 + 52)
#define SMEM_BYTES (SMEM_FLOATS * 4)

struct Consts {
  float c1[11], c0[11];
  float temp, alpha;
  float mix[3];
  float q3g[24];
};
__device__ Consts g_C;
__device__ float g_ph[64 * 256];
__device__ float g_pg[3 * 256];

__device__ __forceinline__ float wsum(float v) {
#pragma unroll
  for (int o = 16; o > 0; o >>= 1) v += __shfl_xor_sync(0xffffffffu, v, o);
  return v;
}
__device__ __forceinline__ float wmaxr(float v) {
#pragma unroll
  for (int o = 16; o > 0; o >>= 1) v = fmaxf(v, __shfl_xor_sync(0xffffffffu, v, o));
  return v;
}

// ---------------- prep: per-weight constants + scalars ----------------
__global__ void prep_kernel(const float* __restrict__ lnw, const float* __restrict__ lnb,
                            const float* __restrict__ wq2, const float* __restrict__ wq3,
                            const float* __restrict__ wq6, const float* __restrict__ lt,
                            const float* __restrict__ lsm, const float* __restrict__ q3in,
                            const float* __restrict__ lwm) {
  int b = blockIdx.x, t = threadIdx.x;
  if (b < 11) {
    __shared__ float s1[256], s0[256];
    const float* w = (b < 2) ? (wq2 + b * D) : (b < 5) ? (wq3 + (b - 2) * D)
                                                       : (wq6 + (b - 5) * D);
    float a1 = 0.f, a0 = 0.f;
    for (int d = t; d < D; d += 256) {
      float wv = w[d];
      a1 += wv * lnw[d];
      a0 += wv * lnb[d];
    }
    s1[t] = a1; s0[t] = a0;
    __syncthreads();
    for (int off = 128; off > 0; off >>= 1) {
      if (t < off) { s1[t] += s1[t + off]; s0[t] += s0[t + off]; }
      __syncthreads();
    }
    if (t == 0) { g_C.c1[b] = s1[0]; g_C.c0[b] = s0[0]; }
  } else if (t == 0) {
    float temp = expf(lt[0]);
    temp = fminf(fmaxf(temp, 0.1f), 5.0f);
    g_C.temp = temp;
    g_C.alpha = 1.0f / (1.0f + expf(-lwm[0]));
    float a = lsm[0], bb = lsm[1], c = lsm[2];
    float m = fmaxf(a, fmaxf(bb, c));
    float ea = expf(a - m), eb = expf(bb - m), ec = expf(c - m);
    float inv = 1.0f / (ea + eb + ec);
    g_C.mix[0] = ea * inv; g_C.mix[1] = eb * inv; g_C.mix[2] = ec * inv;
    for (int v = 0; v < 8; v++) {
      float x0 = q3in[v * 3], x1 = q3in[v * 3 + 1], x2 = q3in[v * 3 + 2];
      float mm = fmaxf(x0, fmaxf(x1, x2));
      float e0 = expf(x0 - mm), e1 = expf(x1 - mm), e2 = expf(x2 - mm);
      float iv = 1.0f / (e0 + e1 + e2);
      g_C.q3g[v * 3 + 0] = e0 * iv;
      g_C.q3g[v * 3 + 1] = e1 * iv;
      g_C.q3g[v * 3 + 2] = e2 * iv;
    }
  }
}

// ---------------- main: 4 rows per block, one pass over x ----------------
__device__ __forceinline__ void dotacc(const float* __restrict__ wrow,
                                       const float xl[RPB][8], float* accr) {
  float4 wa = *(const float4*)(wrow);
  float4 wb = *(const float4*)(wrow + 4);
  float wv[8] = {wa.x, wa.y, wa.z, wa.w, wb.x, wb.y, wb.z, wb.w};
#pragma unroll
  for (int r = 0; r < RPB; r++) {
    float a0 = xl[r][0] * wv[0] + xl[r][1] * wv[1] + xl[r][2] * wv[2] + xl[r][3] * wv[3];
    float a1 = xl[r][4] * wv[4] + xl[r][5] * wv[5] + xl[r][6] * wv[6] + xl[r][7] * wv[7];
    accr[r] += a0 + a1;
  }
}

__global__ void __launch_bounds__(256, 2)
main_kernel(const float* __restrict__ x, const float* __restrict__ lnw,
            const float* __restrict__ wq2, const float* __restrict__ wq3,
            const float* __restrict__ wq6, float* __restrict__ out) {
  extern __shared__ float smem[];
  float* parts = smem;
  float* p2 = smem + 256 * PARTS_STRIDE;
  float* fin = p2 + 208;

  const int t = threadIdx.x;
  const int row0 = blockIdx.x * RPB;
  const int d0 = t * 8;

  float4 lwa = *(const float4*)(lnw + d0);
  float4 lwb = *(const float4*)(lnw + d0 + 4);
  float lw[8] = {lwa.x, lwa.y, lwa.z, lwa.w, lwb.x, lwb.y, lwb.z, lwb.w};

  float xl[RPB][8];
  float ssum[RPB], ssq[RPB];
#pragma unroll
  for (int r = 0; r < RPB; r++) {
    const float* xr = x + (size_t)(row0 + r) * D + d0;
    float4 a = *(const float4*)xr;
    float4 b = *(const float4*)(xr + 4);
    float v[8] = {a.x, a.y, a.z, a.w, b.x, b.y, b.z, b.w};
    float s = 0.f, q = 0.f;
#pragma unroll
    for (int i = 0; i < 8; i++) { s += v[i]; q += v[i] * v[i]; }
    ssum[r] = s; ssq[r] = q;
#pragma unroll
    for (int i = 0; i < 8; i++) xl[r][i] = v[i] * lw[i];
  }

  float acc[11][RPB];
#pragma unroll
  for (int j = 0; j < 11; j++)
#pragma unroll
    for (int r = 0; r < RPB; r++) acc[j][r] = 0.f;

#pragma unroll
  for (int j = 0; j < 2; j++) dotacc(wq2 + j * D + d0, xl, acc[j]);
#pragma unroll
  for (int j = 0; j < 3; j++) dotacc(wq3 + j * D + d0, xl, acc[2 + j]);
#pragma unroll
  for (int j = 0; j < 6; j++) dotacc(wq6 + j * D + d0, xl, acc[5 + j]);

  // transpose partials into shared: parts[t][row*13 + stat], stride 53 => conflict-free
  float* pr = parts + t * PARTS_STRIDE;
#pragma unroll
  for (int r = 0; r < RPB; r++) {
    pr[r * 13 + 0] = ssum[r];
    pr[r * 13 + 1] = ssq[r];
#pragma unroll
    for (int j = 0; j < 11; j++) pr[r * 13 + 2 + j] = acc[j][r];
  }
  __syncthreads();

  if (t < 208) {
    int s = t % 52, q = t / 52;
    float ps = 0.f;
    const float* base = parts + (q * 64) * PARTS_STRIDE + s;
#pragma unroll 8
    for (int i = 0; i < 64; i++) ps += base[i * PARTS_STRIDE];
    p2[q * 52 + s] = ps;
  }
  __syncthreads();
  if (t < 52) fin[t] = p2[t] + p2[52 + t] + p2[104 + t] + p2[156 + t];
  __syncthreads();

  // epilogue: warp w handles row w
  const int wid = t >> 5, lane = t & 31;
  if (wid < RPB) {
    const float* S = fin + wid * 13;
    float sx = S[0], sq = S[1];
    const float invD = 1.0f / (float)D;
    float mu = sx * invD;
    float var = sq * invD - mu * mu;
    float rs = rsqrtf(var + 1e-5f);
    float tj[11];
#pragma unroll
    for (int j = 0; j < 11; j++) {
      float z = rs * (S[2 + j] - mu * g_C.c1[j]) + g_C.c0[j];
      tj[j] = tanhf(z);
    }
    float it = 1.0f / g_C.temp;

    // Q2: 4 vertices (coord0 from bit1, coord1 from bit0), map v->group [2,1,1,0]
    float l2[4];
#pragma unroll
    for (int v = 0; v < 4; v++) {
      float a = (v & 2) ? tj[0] : -tj[0];
      float b = (v & 1) ? tj[1] : -tj[1];
      l2[v] = (a + b) * it;
    }
    float m2 = fmaxf(fmaxf(l2[0], l2[1]), fmaxf(l2[2], l2[3]));
    float e2s[4], s2 = 0.f;
#pragma unroll
    for (int v = 0; v < 4; v++) { e2s[v] = __expf(l2[v] - m2); s2 += e2s[v]; }
    float i2 = 1.0f / s2;
    float sq2[3];
    sq2[0] = e2s[3] * i2;
    sq2[1] = (e2s[1] + e2s[2]) * i2;
    sq2[2] = e2s[0] * i2;

    // Q3: 8 vertices, learned soft map
    float l3[8];
#pragma unroll
    for (int v = 0; v < 8; v++) {
      float s = 0.f;
#pragma unroll
      for (int k = 0; k < 3; k++) s += ((v >> (2 - k)) & 1) ? tj[2 + k] : -tj[2 + k];
      l3[v] = s * it;
    }
    float m3 = l3[0];
#pragma unroll
    for (int v = 1; v < 8; v++) m3 = fmaxf(m3, l3[v]);
    float e3s[8], s3 = 0.f;
#pragma unroll
    for (int v = 0; v < 8; v++) { e3s[v] = __expf(l3[v] - m3); s3 += e3s[v]; }
    float i3 = 1.0f / s3;
    float sq3[3] = {0.f, 0.f, 0.f};
#pragma unroll
    for (int v = 0; v < 8; v++) {
      float wv = e3s[v] * i3;
      sq3[0] += wv * g_C.q3g[v * 3 + 0];
      sq3[1] += wv * g_C.q3g[v * 3 + 1];
      sq3[2] += wv * g_C.q3g[v * 3 + 2];
    }

    // Q6: 64 hexagram vertices, 2 per lane
    const float ANCH[3][6] = {
        {0.44721359549995794f, 0.44721359549995794f, 0.44721359549995794f,
         0.44721359549995794f, 0.44721359549995794f, 0.0f},
        {-0.5f, 0.5f, -0.5f, 0.0f, 0.0f, 0.5f},
        {-0.44721359549995794f, -0.44721359549995794f, 0.0f,
         -0.44721359549995794f, -0.44721359549995794f, -0.44721359549995794f}};
    int v0 = lane, v1 = lane + 32;
    float l60 = 0.f, l61 = 0.f;
#pragma unroll
    for (int k = 0; k < 6; k++) {
      float tk = tj[5 + k];
      l60 += ((v0 >> (5 - k)) & 1) ? tk : -tk;
      l61 += ((v1 >> (5 - k)) & 1) ? tk : -tk;
    }
    l60 *= it; l61 *= it;
    float mh = wmaxr(fmaxf(l60, l61));
    float e60 = __expf(l60 - mh), e61 = __expf(l61 - mh);
    float sh = wsum(e60 + e61);
    float ih = 1.0f / sh;
    float hw0 = e60 * ih, hw1 = e61 * ih;

    float cg[3] = {0.f, 0.f, 0.f}, wg[3] = {0.f, 0.f, 0.f};
#pragma unroll
    for (int p = 0; p < 2; p++) {
      int v = p ? v1 : v0;
      float hw = p ? hw1 : hw0;
#pragma unroll
      for (int g = 0; g < 3; g++) {
        float dv = 0.f;
#pragma unroll
        for (int k = 0; k < 6; k++)
          dv += (((v >> (5 - k)) & 1) ? ANCH[g][k] : -ANCH[g][k]);
        cg[g] += hw * dv;
      }
      int pc = __popc(v);
      if (pc >= 5) wg[0] += hw * (1.0f / 7.0f);
      if (pc == 3) wg[1] += hw * (1.0f / 20.0f);
      if (pc <= 1) wg[2] += hw * (1.0f / 7.0f);
    }
#pragma unroll
    for (int g = 0; g < 3; g++) { cg[g] = wsum(cg[g]); wg[g] = wsum(wg[g]); }

    float al = g_C.alpha;
    float gl[3];
#pragma unroll
    for (int g = 0; g < 3; g++) {
      float sq6 = (1.0f - al) * cg[g] + al * wg[g];
      gl[g] = g_C.mix[0] * sq2[g] + g_C.mix[1] * sq3[g] + g_C.mix[2] * sq6;
    }
    float mg = fmaxf(gl[0], fmaxf(gl[1], gl[2]));
    float eg0 = __expf(gl[0] - mg), eg1 = __expf(gl[1] - mg), eg2 = __expf(gl[2] - mg);
    float ig = 1.0f / (eg0 + eg1 + eg2);

    int row = row0 + wid;
    out[HEX_OFF + (size_t)row * 64 + lane] = hw0;
    out[HEX_OFF + (size_t)row * 64 + lane + 32] = hw1;
    if (lane == 0) {
      out[(size_t)row * 3 + 0] = eg0 * ig;
      out[(size_t)row * 3 + 1] = eg1 * ig;
      out[(size_t)row * 3 + 2] = eg2 * ig;
    }
  }
}

// ---------------- deterministic mean reduction over outputs ----------------
__global__ void reduce_kernel(const float* __restrict__ out) {
  __shared__ float sh[4][64];
  int b = blockIdx.x, t = threadIdx.x;
  int base = b * 64;
  const float* hex = out + HEX_OFF;
  int c = t & 63, g = t >> 6;
  float s = 0.f;
#pragma unroll
  for (int k = 0; k < 16; k++) s += hex[(size_t)(base + g * 16 + k) * 64 + c];
  sh[g][c] = s;
  __syncthreads();
  if (t < 64) g_ph[t * 256 + b] = sh[0][t] + sh[1][t] + sh[2][t] + sh[3][t];
  if (t < 3) {
    float gs = 0.f;
    for (int k = 0; k < 64; k++) gs += out[(size_t)(base + k) * 3 + t];
    g_pg[t * 256 + b] = gs;
  }
}

__global__ void final_kernel(float* __restrict__ out) {
  __shared__ float contrib[67];
  int t = threadIdx.x;
  if (t < 64) {
    float s = 0.f;
    for (int b = 0; b < 256; b++) s += g_ph[t * 256 + b];
    float mh = s * (1.0f / 16384.0f);
    contrib[t] = 0.1f * mh * logf(mh + 1e-8f);
  } else if (t < 67) {
    int c = t - 64;
    float s = 0.f;
    for (int b = 0; b < 256; b++) s += g_pg[c * 256 + b];
    float mg = s * (1.0f / 16384.0f);
    contrib[t] = mg * logf(mg + 1e-8f);
  }
  __syncthreads();
  if (t == 0) {
    float lb = 0.f;
    for (int i = 0; i < 67; i++) lb += contrib[i];
    out[LB_OFF] = lb;
  }
}

extern "C" void kernel_launch(void* const* d_in, const int* in_sizes, int n_in,
                              void* d_out, int out_size) {
  const float* x   = (const float*)d_in[0];
  const float* lnw = (const float*)d_in[1];
  const float* lnb = (const float*)d_in[2];
  const float* wq2 = (const float*)d_in[3];
  const float* wq3 = (const float*)d_in[4];
  const float* wq6 = (const float*)d_in[5];
  const float* lt  = (const float*)d_in[6];
  const float* lsm = (const float*)d_in[7];
  const float* q3g = (const float*)d_in[8];
  const float* lwm = (const float*)d_in[9];
  float* out = (float*)d_out;

  cudaFuncSetAttribute(main_kernel, cudaFuncAttributeMaxDynamicSharedMemorySize,
                       SMEM_BYTES);
  prep_kernel<<<12, 256>>>(lnw, lnb, wq2, wq3, wq6, lt, lsm, q3g, lwm);
  main_kernel<<<NBLOCKS, 256, SMEM_BYTES>>>(x, lnw, wq2, wq3, wq6, out);
  reduce_kernel<<<256, 256>>>(out);
  final_kernel<<<1, 128>>>(out);
}

// round 3
// speedup vs baseline: 1.1061x; 1.1061x over previous
#include <cuda_runtime.h>
#include <cstdint>

#define D 2048
#define NROWS 16384
#define TILE 4
#define NTILES (NROWS / TILE)   // 4096
#define GRID 296
#define THREADS 256

#define GRP_OFF 0
#define HEX_OFF (NROWS * 3)
#define LB_OFF (HEX_OFF + NROWS * 64)

#define PARTS_STRIDE 53
// smem: parts[256*53] | p2[208] | fin[52] | comb[256] | combg[12]
#define SMEM_FLOATS (256 * PARTS_STRIDE + 208 + 52 + 256 + 12)
#define SMEM_BYTES (SMEM_FLOATS * 4)

struct Consts {
  float c1[11], c0[11];
  float temp, alpha;
  float mix[3];
  float q3g[24];
};
__device__ Consts g_C;
__device__ float g_ph[GRID * 64];
__device__ float g_pg[GRID * 3];
__device__ unsigned g_ctr;  // zero-init; last block resets to 0 each run

// ---------- packed f32x2 helpers ----------
__device__ __forceinline__ void FMA2(uint64_t& d, uint64_t a, uint64_t b) {
  asm("fma.rn.f32x2 %0, %1, %2, %0;" : "+l"(d) : "l"(a), "l"(b));
}
__device__ __forceinline__ void ADD2(uint64_t& d, uint64_t a) {
  asm("add.rn.f32x2 %0, %0, %1;" : "+l"(d) : "l"(a));
}
__device__ __forceinline__ uint64_t MUL2(uint64_t a, uint64_t b) {
  uint64_t r;
  asm("mul.rn.f32x2 %0, %1, %2;" : "=l"(r) : "l"(a), "l"(b));
  return r;
}
__device__ __forceinline__ float PSUM(uint64_t v) {
  float a, b;
  asm("mov.b64 {%0,%1}, %2;" : "=f"(a), "=f"(b) : "l"(v));
  return a + b;
}

__device__ __forceinline__ float wsum(float v) {
#pragma unroll
  for (int o = 16; o > 0; o >>= 1) v += __shfl_xor_sync(0xffffffffu, v, o);
  return v;
}
__device__ __forceinline__ float wmaxr(float v) {
#pragma unroll
  for (int o = 16; o > 0; o >>= 1) v = fmaxf(v, __shfl_xor_sync(0xffffffffu, v, o));
  return v;
}

// ---------------- prep: per-weight constants + scalars ----------------
__global__ void prep_kernel(const float* __restrict__ lnw, const float* __restrict__ lnb,
                            const float* __restrict__ wq2, const float* __restrict__ wq3,
                            const float* __restrict__ wq6, const float* __restrict__ lt,
                            const float* __restrict__ lsm, const float* __restrict__ q3in,
                            const float* __restrict__ lwm) {
  int b = blockIdx.x, t = threadIdx.x;
  if (b < 11) {
    __shared__ float s1[256], s0[256];
    const float* w = (b < 2) ? (wq2 + b * D) : (b < 5) ? (wq3 + (b - 2) * D)
                                                       : (wq6 + (b - 5) * D);
    float a1 = 0.f, a0 = 0.f;
    for (int d = t; d < D; d += 256) {
      float wv = w[d];
      a1 += wv * lnw[d];
      a0 += wv * lnb[d];
    }
    s1[t] = a1; s0[t] = a0;
    __syncthreads();
    for (int off = 128; off > 0; off >>= 1) {
      if (t < off) { s1[t] += s1[t + off]; s0[t] += s0[t + off]; }
      __syncthreads();
    }
    if (t == 0) { g_C.c1[b] = s1[0]; g_C.c0[b] = s0[0]; }
  } else if (t == 0) {
    float temp = expf(lt[0]);
    temp = fminf(fmaxf(temp, 0.1f), 5.0f);
    g_C.temp = temp;
    g_C.alpha = 1.0f / (1.0f + expf(-lwm[0]));
    float a = lsm[0], bb = lsm[1], c = lsm[2];
    float m = fmaxf(a, fmaxf(bb, c));
    float ea = expf(a - m), eb = expf(bb - m), ec = expf(c - m);
    float inv = 1.0f / (ea + eb + ec);
    g_C.mix[0] = ea * inv; g_C.mix[1] = eb * inv; g_C.mix[2] = ec * inv;
    for (int v = 0; v < 8; v++) {
      float x0 = q3in[v * 3], x1 = q3in[v * 3 + 1], x2 = q3in[v * 3 + 2];
      float mm = fmaxf(x0, fmaxf(x1, x2));
      float e0 = expf(x0 - mm), e1 = expf(x1 - mm), e2 = expf(x2 - mm);
      float iv = 1.0f / (e0 + e1 + e2);
      g_C.q3g[v * 3 + 0] = e0 * iv;
      g_C.q3g[v * 3 + 1] = e1 * iv;
      g_C.q3g[v * 3 + 2] = e2 * iv;
    }
  }
}

// ---------------- main ----------------
__device__ __forceinline__ void loadtile(uint64_t X[16], const float* __restrict__ x,
                                         int tile, int d0) {
#pragma unroll
  for (int r = 0; r < TILE; r++) {
    const float* p = x + ((size_t)tile * TILE + r) * D + d0;
    ulonglong2 a = *(const ulonglong2*)p;
    ulonglong2 b = *(const ulonglong2*)(p + 4);
    X[r * 4 + 0] = a.x; X[r * 4 + 1] = a.y;
    X[r * 4 + 2] = b.x; X[r * 4 + 3] = b.y;
  }
}

__global__ void __launch_bounds__(THREADS, 1)
main_kernel(const float* __restrict__ x, const float* __restrict__ lnw,
            const float* __restrict__ wq2, const float* __restrict__ wq3,
            const float* __restrict__ wq6, float* __restrict__ out) {
  extern __shared__ float smem[];
  float* parts = smem;
  float* p2 = smem + 256 * PARTS_STRIDE;
  float* fin = p2 + 208;
  float* comb = fin + 52;
  float* combg = comb + 256;

  const int t = threadIdx.x;
  const int wid = t >> 5, lane = t & 31;
  const int d0 = t * 8;

  // load lnw pairs, then 11 weight rows premultiplied by lnw (registers)
  uint64_t lnp[4];
  {
    ulonglong2 a = *(const ulonglong2*)(lnw + d0);
    ulonglong2 b = *(const ulonglong2*)(lnw + d0 + 4);
    lnp[0] = a.x; lnp[1] = a.y; lnp[2] = b.x; lnp[3] = b.y;
  }
  uint64_t wm[11][4];
#pragma unroll
  for (int j = 0; j < 11; j++) {
    const float* wr = ((j < 2) ? (wq2 + j * D) : (j < 5) ? (wq3 + (j - 2) * D)
                                                         : (wq6 + (j - 5) * D)) + d0;
    ulonglong2 a = *(const ulonglong2*)wr;
    ulonglong2 b = *(const ulonglong2*)(wr + 4);
    wm[j][0] = MUL2(a.x, lnp[0]);
    wm[j][1] = MUL2(a.y, lnp[1]);
    wm[j][2] = MUL2(b.x, lnp[2]);
    wm[j][3] = MUL2(b.y, lnp[3]);
  }

  // lb_loss accumulators
  float hxa0 = 0.f, hxa1 = 0.f, ga0 = 0.f, ga1 = 0.f, ga2 = 0.f;

  uint64_t X[16];
  loadtile(X, x, blockIdx.x, d0);

  for (int tile = blockIdx.x; tile < NTILES; tile += GRID) {
    // prefetch next tile early: latency hidden under compute+reduce
    uint64_t XN[16];
    int nt = tile + GRID;
    bool have_next = (nt < NTILES);
    if (have_next) loadtile(XN, x, nt, d0);

    float* pr = parts + t * PARTS_STRIDE;
#pragma unroll
    for (int r = 0; r < TILE; r++) {
      uint64_t as = 0ull, aq = 0ull;
      uint64_t ad[11];
#pragma unroll
      for (int j = 0; j < 11; j++) ad[j] = 0ull;
#pragma unroll
      for (int p = 0; p < 4; p++) {
        uint64_t xv = X[r * 4 + p];
        ADD2(as, xv);
        FMA2(aq, xv, xv);
#pragma unroll
        for (int j = 0; j < 11; j++) FMA2(ad[j], xv, wm[j][p]);
      }
      pr[r * 13 + 0] = PSUM(as);
      pr[r * 13 + 1] = PSUM(aq);
#pragma unroll
      for (int j = 0; j < 11; j++) pr[r * 13 + 2 + j] = PSUM(ad[j]);
    }
    __syncthreads();

    if (t < 208) {
      int s = t % 52, q = t / 52;
      float ps = 0.f;
      const float* base = parts + (q * 64) * PARTS_STRIDE + s;
#pragma unroll 8
      for (int i = 0; i < 64; i++) ps += base[i * PARTS_STRIDE];
      p2[q * 52 + s] = ps;
    }
    __syncthreads();
    if (t < 52) fin[t] = p2[t] + p2[52 + t] + p2[104 + t] + p2[156 + t];
    __syncthreads();

    // ---- epilogue: warp w handles row w of the tile ----
    if (wid < TILE) {
      const float* S = fin + wid * 13;
      float sx = S[0], sq = S[1];
      const float invD = 1.0f / (float)D;
      float mu = sx * invD;
      float var = sq * invD - mu * mu;
      float rs = rsqrtf(var + 1e-5f);
      float tj[11];
#pragma unroll
      for (int j = 0; j < 11; j++) {
        float z = rs * (S[2 + j] - mu * g_C.c1[j]) + g_C.c0[j];
        tj[j] = tanhf(z);
      }
      float it = 1.0f / g_C.temp;

      // Q2
      float l2[4];
#pragma unroll
      for (int v = 0; v < 4; v++) {
        float a = (v & 2) ? tj[0] : -tj[0];
        float b = (v & 1) ? tj[1] : -tj[1];
        l2[v] = (a + b) * it;
      }
      float m2 = fmaxf(fmaxf(l2[0], l2[1]), fmaxf(l2[2], l2[3]));
      float e2s[4], s2 = 0.f;
#pragma unroll
      for (int v = 0; v < 4; v++) { e2s[v] = __expf(l2[v] - m2); s2 += e2s[v]; }
      float i2 = 1.0f / s2;
      float sq2[3];
      sq2[0] = e2s[3] * i2;
      sq2[1] = (e2s[1] + e2s[2]) * i2;
      sq2[2] = e2s[0] * i2;

      // Q3
      float l3[8];
#pragma unroll
      for (int v = 0; v < 8; v++) {
        float s = 0.f;
#pragma unroll
        for (int k = 0; k < 3; k++) s += ((v >> (2 - k)) & 1) ? tj[2 + k] : -tj[2 + k];
        l3[v] = s * it;
      }
      float m3 = l3[0];
#pragma unroll
      for (int v = 1; v < 8; v++) m3 = fmaxf(m3, l3[v]);
      float e3s[8], s3 = 0.f;
#pragma unroll
      for (int v = 0; v < 8; v++) { e3s[v] = __expf(l3[v] - m3); s3 += e3s[v]; }
      float i3 = 1.0f / s3;
      float sq3[3] = {0.f, 0.f, 0.f};
#pragma unroll
      for (int v = 0; v < 8; v++) {
        float wv = e3s[v] * i3;
        sq3[0] += wv * g_C.q3g[v * 3 + 0];
        sq3[1] += wv * g_C.q3g[v * 3 + 1];
        sq3[2] += wv * g_C.q3g[v * 3 + 2];
      }

      // Q6: 64 vertices, 2 per lane
      const float ANCH[3][6] = {
          {0.44721359549995794f, 0.44721359549995794f, 0.44721359549995794f,
           0.44721359549995794f, 0.44721359549995794f, 0.0f},
          {-0.5f, 0.5f, -0.5f, 0.0f, 0.0f, 0.5f},
          {-0.44721359549995794f, -0.44721359549995794f, 0.0f,
           -0.44721359549995794f, -0.44721359549995794f, -0.44721359549995794f}};
      int v0 = lane, v1 = lane + 32;
      float l60 = 0.f, l61 = 0.f;
#pragma unroll
      for (int k = 0; k < 6; k++) {
        float tk = tj[5 + k];
        l60 += ((v0 >> (5 - k)) & 1) ? tk : -tk;
        l61 += ((v1 >> (5 - k)) & 1) ? tk : -tk;
      }
      l60 *= it; l61 *= it;
      float mh = wmaxr(fmaxf(l60, l61));
      float e60 = __expf(l60 - mh), e61 = __expf(l61 - mh);
      float sh = wsum(e60 + e61);
      float ih = 1.0f / sh;
      float hw0 = e60 * ih, hw1 = e61 * ih;

      float cg[3] = {0.f, 0.f, 0.f}, wg[3] = {0.f, 0.f, 0.f};
#pragma unroll
      for (int p = 0; p < 2; p++) {
        int v = p ? v1 : v0;
        float hw = p ? hw1 : hw0;
#pragma unroll
        for (int g = 0; g < 3; g++) {
          float dv = 0.f;
#pragma unroll
          for (int k = 0; k < 6; k++)
            dv += (((v >> (5 - k)) & 1) ? ANCH[g][k] : -ANCH[g][k]);
          cg[g] += hw * dv;
        }
        int pc = __popc(v);
        if (pc >= 5) wg[0] += hw * (1.0f / 7.0f);
        if (pc == 3) wg[1] += hw * (1.0f / 20.0f);
        if (pc <= 1) wg[2] += hw * (1.0f / 7.0f);
      }
#pragma unroll
      for (int g = 0; g < 3; g++) { cg[g] = wsum(cg[g]); wg[g] = wsum(wg[g]); }

      float al = g_C.alpha;
      float gl[3];
#pragma unroll
      for (int g = 0; g < 3; g++) {
        float sq6 = (1.0f - al) * cg[g] + al * wg[g];
        gl[g] = g_C.mix[0] * sq2[g] + g_C.mix[1] * sq3[g] + g_C.mix[2] * sq6;
      }
      float mg = fmaxf(gl[0], fmaxf(gl[1], gl[2]));
      float eg0 = __expf(gl[0] - mg), eg1 = __expf(gl[1] - mg), eg2 = __expf(gl[2] - mg);
      float ig = 1.0f / (eg0 + eg1 + eg2);

      int row = tile * TILE + wid;
      out[HEX_OFF + (size_t)row * 64 + lane] = hw0;
      out[HEX_OFF + (size_t)row * 64 + lane + 32] = hw1;
      hxa0 += hw0;
      hxa1 += hw1;
      if (lane == 0) {
        float g0 = eg0 * ig, g1 = eg1 * ig, g2 = eg2 * ig;
        out[(size_t)row * 3 + 0] = g0;
        out[(size_t)row * 3 + 1] = g1;
        out[(size_t)row * 3 + 2] = g2;
        ga0 += g0; ga1 += g1; ga2 += g2;
      }
    }

    if (have_next) {
#pragma unroll
      for (int i = 0; i < 16; i++) X[i] = XN[i];
    }
  }

  // ---- per-block combine of lb accumulators ----
  __syncthreads();
  if (wid < TILE) {
    comb[wid * 64 + lane] = hxa0;
    comb[wid * 64 + lane + 32] = hxa1;
    if (lane == 0) {
      combg[wid * 3 + 0] = ga0;
      combg[wid * 3 + 1] = ga1;
      combg[wid * 3 + 2] = ga2;
    }
  }
  __syncthreads();
  if (t < 64)
    g_ph[blockIdx.x * 64 + t] = comb[t] + comb[64 + t] + comb[128 + t] + comb[192 + t];
  if (t < 3)
    g_pg[blockIdx.x * 3 + t] = combg[t] + combg[3 + t] + combg[6 + t] + combg[9 + t];

  // ---- fused final reduction: last block computes lb_loss ----
  __shared__ unsigned is_last;
  __threadfence();
  if (t == 0) {
    unsigned v = atomicAdd(&g_ctr, 1u);
    is_last = (v == GRID - 1) ? 1u : 0u;
  }
  __syncthreads();
  if (is_last) {
    int c = t & 63, st = t >> 6;  // 296 = 4 * 74
    const float* base = g_ph + (size_t)(st * 74) * 64 + c;
    float s = 0.f;
    for (int b = 0; b < 74; b++) s += base[b * 64];
    comb[st * 64 + c] = s;
    __syncthreads();
    if (t < 64) {
      float mh = (comb[t] + comb[64 + t] + comb[128 + t] + comb[192 + t]) *
                 (1.0f / (float)NROWS);
      p2[t] = 0.1f * mh * logf(mh + 1e-8f);
    } else if (t < 67) {
      int g = t - 64;
      float sg = 0.f;
      for (int b = 0; b < GRID; b++) sg += g_pg[b * 3 + g];
      float mg = sg * (1.0f / (float)NROWS);
      p2[t] = mg * logf(mg + 1e-8f);
    }
    __syncthreads();
    if (t == 0) {
      float lb = 0.f;
      for (int i = 0; i < 67; i++) lb += p2[i];
      out[LB_OFF] = lb;
      g_ctr = 0;  // reset for next graph replay
    }
  }
}

extern "C" void kernel_launch(void* const* d_in, const int* in_sizes, int n_in,
                              void* d_out, int out_size) {
  const float* x   = (const float*)d_in[0];
  const float* lnw = (const float*)d_in[1];
  const float* lnb = (const float*)d_in[2];
  const float* wq2 = (const float*)d_in[3];
  const float* wq3 = (const float*)d_in[4];
  const float* wq6 = (const float*)d_in[5];
  const float* lt  = (const float*)d_in[6];
  const float* lsm = (const float*)d_in[7];
  const float* q3g = (const float*)d_in[8];
  const float* lwm = (const float*)d_in[9];
  float* out = (float*)d_out;

  cudaFuncSetAttribute(main_kernel, cudaFuncAttributeMaxDynamicSharedMemorySize,
                       SMEM_BYTES);
  prep_kernel<<<12, 256>>>(lnw, lnb, wq2, wq3, wq6, lt, lsm, q3g, lwm);
  main_kernel<<<GRID, THREADS, SMEM_BYTES>>>(x, lnw, wq2, wq3, wq6, out);
}

// round 4
// speedup vs baseline: 1.3660x; 1.2350x over previous
#include <cuda_runtime.h>
#include <cstdint>

#define D 2048
#define NROWS 16384
#define TILE 8
#define NTILES (NROWS / TILE)   // 2048
#define GRID 148
#define THREADS 256
#define NSTAT 13
#define TSTAT (TILE * NSTAT)    // 104

#define HEX_OFF (NROWS * 3)
#define LB_OFF (HEX_OFF + NROWS * 64)

#define PARTS_STRIDE 105        // odd => conflict-free column walks
// smem: parts[256*105] | p2[416] | fin[104] | comb[512] | combg[24]
#define SMEM_FLOATS (256 * PARTS_STRIDE + 416 + 104 + 512 + 24)
#define SMEM_BYTES (SMEM_FLOATS * 4)

struct Consts {
  float c1[11], c0[11];
  float temp, alpha;
  float mix[3];
  float q3g[24];
};
__device__ Consts g_C;
__device__ float g_ph[GRID * 64];
__device__ float g_pg[GRID * 3];
__device__ unsigned g_ctr;  // zero-init; last block resets each run

// ---------- packed f32x2 helpers ----------
__device__ __forceinline__ void FMA2(uint64_t& d, uint64_t a, uint64_t b) {
  asm("fma.rn.f32x2 %0, %1, %2, %0;" : "+l"(d) : "l"(a), "l"(b));
}
__device__ __forceinline__ void ADD2(uint64_t& d, uint64_t a) {
  asm("add.rn.f32x2 %0, %0, %1;" : "+l"(d) : "l"(a));
}
__device__ __forceinline__ uint64_t MUL2(uint64_t a, uint64_t b) {
  uint64_t r;
  asm("mul.rn.f32x2 %0, %1, %2;" : "=l"(r) : "l"(a), "l"(b));
  return r;
}
__device__ __forceinline__ float PSUM(uint64_t v) {
  float a, b;
  asm("mov.b64 {%0,%1}, %2;" : "=f"(a), "=f"(b) : "l"(v));
  return a + b;
}

__device__ __forceinline__ float wsum(float v) {
#pragma unroll
  for (int o = 16; o > 0; o >>= 1) v += __shfl_xor_sync(0xffffffffu, v, o);
  return v;
}
__device__ __forceinline__ float wmaxr(float v) {
#pragma unroll
  for (int o = 16; o > 0; o >>= 1) v = fmaxf(v, __shfl_xor_sync(0xffffffffu, v, o));
  return v;
}

// ---------------- prep ----------------
__global__ void prep_kernel(const float* __restrict__ lnw, const float* __restrict__ lnb,
                            const float* __restrict__ wq2, const float* __restrict__ wq3,
                            const float* __restrict__ wq6, const float* __restrict__ lt,
                            const float* __restrict__ lsm, const float* __restrict__ q3in,
                            const float* __restrict__ lwm) {
  int b = blockIdx.x, t = threadIdx.x;
  if (b < 11) {
    __shared__ float s1[256], s0[256];
    const float* w = (b < 2) ? (wq2 + b * D) : (b < 5) ? (wq3 + (b - 2) * D)
                                                       : (wq6 + (b - 5) * D);
    float a1 = 0.f, a0 = 0.f;
    for (int d = t; d < D; d += 256) {
      float wv = w[d];
      a1 += wv * lnw[d];
      a0 += wv * lnb[d];
    }
    s1[t] = a1; s0[t] = a0;
    __syncthreads();
    for (int off = 128; off > 0; off >>= 1) {
      if (t < off) { s1[t] += s1[t + off]; s0[t] += s0[t + off]; }
      __syncthreads();
    }
    if (t == 0) { g_C.c1[b] = s1[0]; g_C.c0[b] = s0[0]; }
  } else if (t == 0) {
    float temp = expf(lt[0]);
    temp = fminf(fmaxf(temp, 0.1f), 5.0f);
    g_C.temp = temp;
    g_C.alpha = 1.0f / (1.0f + expf(-lwm[0]));
    float a = lsm[0], bb = lsm[1], c = lsm[2];
    float m = fmaxf(a, fmaxf(bb, c));
    float ea = expf(a - m), eb = expf(bb - m), ec = expf(c - m);
    float inv = 1.0f / (ea + eb + ec);
    g_C.mix[0] = ea * inv; g_C.mix[1] = eb * inv; g_C.mix[2] = ec * inv;
    for (int v = 0; v < 8; v++) {
      float x0 = q3in[v * 3], x1 = q3in[v * 3 + 1], x2 = q3in[v * 3 + 2];
      float mm = fmaxf(x0, fmaxf(x1, x2));
      float e0 = expf(x0 - mm), e1 = expf(x1 - mm), e2 = expf(x2 - mm);
      float iv = 1.0f / (e0 + e1 + e2);
      g_C.q3g[v * 3 + 0] = e0 * iv;
      g_C.q3g[v * 3 + 1] = e1 * iv;
      g_C.q3g[v * 3 + 2] = e2 * iv;
    }
  }
}

// ---------------- main ----------------
__device__ __forceinline__ void loadtile(uint64_t X[TILE * 4], const float* __restrict__ x,
                                         int tile, int d0) {
#pragma unroll
  for (int r = 0; r < TILE; r++) {
    const float* p = x + ((size_t)tile * TILE + r) * D + d0;
    ulonglong2 a = *(const ulonglong2*)p;
    ulonglong2 b = *(const ulonglong2*)(p + 4);
    X[r * 4 + 0] = a.x; X[r * 4 + 1] = a.y;
    X[r * 4 + 2] = b.x; X[r * 4 + 3] = b.y;
  }
}

__global__ void __launch_bounds__(THREADS, 1)
main_kernel(const float* __restrict__ x, const float* __restrict__ lnw,
            const float* __restrict__ wq2, const float* __restrict__ wq3,
            const float* __restrict__ wq6, float* __restrict__ out) {
  extern __shared__ float smem[];
  float* parts = smem;
  float* p2 = smem + 256 * PARTS_STRIDE;
  float* fin = p2 + 416;
  float* comb = fin + 104;
  float* combg = comb + 512;

  const int t = threadIdx.x;
  const int wid = t >> 5, lane = t & 31;
  const int d0 = t * 8;

  // weights premultiplied by lnw, register-resident as f32x2
  uint64_t wm[11][4];
  {
    ulonglong2 a = *(const ulonglong2*)(lnw + d0);
    ulonglong2 b = *(const ulonglong2*)(lnw + d0 + 4);
    uint64_t lnp[4] = {a.x, a.y, b.x, b.y};
#pragma unroll
    for (int j = 0; j < 11; j++) {
      const float* wr = ((j < 2) ? (wq2 + j * D) : (j < 5) ? (wq3 + (j - 2) * D)
                                                           : (wq6 + (j - 5) * D)) + d0;
      ulonglong2 wa = *(const ulonglong2*)wr;
      ulonglong2 wb = *(const ulonglong2*)(wr + 4);
      wm[j][0] = MUL2(wa.x, lnp[0]);
      wm[j][1] = MUL2(wa.y, lnp[1]);
      wm[j][2] = MUL2(wb.x, lnp[2]);
      wm[j][3] = MUL2(wb.y, lnp[3]);
    }
  }

  float hxa0 = 0.f, hxa1 = 0.f, ga0 = 0.f, ga1 = 0.f, ga2 = 0.f;

  uint64_t X[TILE * 4];
  loadtile(X, x, blockIdx.x, d0);

  for (int tile = blockIdx.x; tile < NTILES; tile += GRID) {
    // ---- phase 1: partial stats per thread, per row ----
    float* pr = parts + t * PARTS_STRIDE;
#pragma unroll
    for (int r = 0; r < TILE; r++) {
      uint64_t as = 0ull, aq = 0ull;
      uint64_t ad[11];
#pragma unroll
      for (int j = 0; j < 11; j++) ad[j] = 0ull;
#pragma unroll
      for (int p = 0; p < 4; p++) {
        uint64_t xv = X[r * 4 + p];
        ADD2(as, xv);
        FMA2(aq, xv, xv);
#pragma unroll
        for (int j = 0; j < 11; j++) FMA2(ad[j], xv, wm[j][p]);
      }
      pr[r * NSTAT + 0] = PSUM(as);
      pr[r * NSTAT + 1] = PSUM(aq);
#pragma unroll
      for (int j = 0; j < 11; j++) pr[r * NSTAT + 2 + j] = PSUM(ad[j]);
    }

    // ---- prefetch next tile into X (latency hidden by reduce+epilogue) ----
    {
      int nt = tile + GRID;
      if (nt < NTILES) loadtile(X, x, nt, d0);
    }
    __syncthreads();

    // ---- phase 2: 416 tasks (4 chunks x 104 stats), 64-deep sums ----
    {
      int id = t;
      if (id < 208) {
#pragma unroll
        for (int rep = 0; rep < 2; rep++) {
          int q = id / TSTAT, s = id % TSTAT;
          const float* base = parts + (q * 64) * PARTS_STRIDE + s;
          float ps = 0.f;
#pragma unroll 8
          for (int i = 0; i < 64; i++) ps += base[i * PARTS_STRIDE];
          p2[id] = ps;
          id += 208;
        }
      }
    }
    __syncthreads();
    if (t < TSTAT)
      fin[t] = p2[t] + p2[t + TSTAT] + p2[t + 2 * TSTAT] + p2[t + 3 * TSTAT];
    __syncthreads();

    // ---- epilogue: warp w handles row w (all 8 warps busy) ----
    {
      const float* S = fin + wid * NSTAT;
      float sx = S[0], sq = S[1];
      const float invD = 1.0f / (float)D;
      float mu = sx * invD;
      float var = sq * invD - mu * mu;
      float rs = rsqrtf(var + 1e-5f);

      // distributed tanh: lane j computes stat j, broadcast
      float tv = 0.f;
      if (lane < 11) {
        float z = rs * (S[2 + lane] - mu * g_C.c1[lane]) + g_C.c0[lane];
        tv = tanhf(z);
      }
      float tj[11];
#pragma unroll
      for (int j = 0; j < 11; j++) tj[j] = __shfl_sync(0xffffffffu, tv, j);

      float it = 1.0f / g_C.temp;

      // Q2
      float l2[4];
#pragma unroll
      for (int v = 0; v < 4; v++) {
        float a = (v & 2) ? tj[0] : -tj[0];
        float b = (v & 1) ? tj[1] : -tj[1];
        l2[v] = (a + b) * it;
      }
      float m2 = fmaxf(fmaxf(l2[0], l2[1]), fmaxf(l2[2], l2[3]));
      float e2s[4], s2 = 0.f;
#pragma unroll
      for (int v = 0; v < 4; v++) { e2s[v] = __expf(l2[v] - m2); s2 += e2s[v]; }
      float i2 = 1.0f / s2;
      float sq2[3];
      sq2[0] = e2s[3] * i2;
      sq2[1] = (e2s[1] + e2s[2]) * i2;
      sq2[2] = e2s[0] * i2;

      // Q3
      float l3[8];
#pragma unroll
      for (int v = 0; v < 8; v++) {
        float s = 0.f;
#pragma unroll
        for (int k = 0; k < 3; k++) s += ((v >> (2 - k)) & 1) ? tj[2 + k] : -tj[2 + k];
        l3[v] = s * it;
      }
      float m3 = l3[0];
#pragma unroll
      for (int v = 1; v < 8; v++) m3 = fmaxf(m3, l3[v]);
      float e3s[8], s3 = 0.f;
#pragma unroll
      for (int v = 0; v < 8; v++) { e3s[v] = __expf(l3[v] - m3); s3 += e3s[v]; }
      float i3 = 1.0f / s3;
      float sq3[3] = {0.f, 0.f, 0.f};
#pragma unroll
      for (int v = 0; v < 8; v++) {
        float wv = e3s[v] * i3;
        sq3[0] += wv * g_C.q3g[v * 3 + 0];
        sq3[1] += wv * g_C.q3g[v * 3 + 1];
        sq3[2] += wv * g_C.q3g[v * 3 + 2];
      }

      // Q6
      const float ANCH[3][6] = {
          {0.44721359549995794f, 0.44721359549995794f, 0.44721359549995794f,
           0.44721359549995794f, 0.44721359549995794f, 0.0f},
          {-0.5f, 0.5f, -0.5f, 0.0f, 0.0f, 0.5f},
          {-0.44721359549995794f, -0.44721359549995794f, 0.0f,
           -0.44721359549995794f, -0.44721359549995794f, -0.44721359549995794f}};
      int v0 = lane, v1 = lane + 32;
      float l60 = 0.f, l61 = 0.f;
#pragma unroll
      for (int k = 0; k < 6; k++) {
        float tk = tj[5 + k];
        l60 += ((v0 >> (5 - k)) & 1) ? tk : -tk;
        l61 += ((v1 >> (5 - k)) & 1) ? tk : -tk;
      }
      l60 *= it; l61 *= it;
      float mh = wmaxr(fmaxf(l60, l61));
      float e60 = __expf(l60 - mh), e61 = __expf(l61 - mh);
      float sh = wsum(e60 + e61);
      float ih = 1.0f / sh;
      float hw0 = e60 * ih, hw1 = e61 * ih;

      float cg[3] = {0.f, 0.f, 0.f}, wg[3] = {0.f, 0.f, 0.f};
#pragma unroll
      for (int p = 0; p < 2; p++) {
        int v = p ? v1 : v0;
        float hw = p ? hw1 : hw0;
#pragma unroll
        for (int g = 0; g < 3; g++) {
          float dv = 0.f;
#pragma unroll
          for (int k = 0; k < 6; k++)
            dv += (((v >> (5 - k)) & 1) ? ANCH[g][k] : -ANCH[g][k]);
          cg[g] += hw * dv;
        }
        int pc = __popc(v);
        if (pc >= 5) wg[0] += hw * (1.0f / 7.0f);
        if (pc == 3) wg[1] += hw * (1.0f / 20.0f);
        if (pc <= 1) wg[2] += hw * (1.0f / 7.0f);
      }
#pragma unroll
      for (int g = 0; g < 3; g++) { cg[g] = wsum(cg[g]); wg[g] = wsum(wg[g]); }

      float al = g_C.alpha;
      float gl[3];
#pragma unroll
      for (int g = 0; g < 3; g++) {
        float sq6 = (1.0f - al) * cg[g] + al * wg[g];
        gl[g] = g_C.mix[0] * sq2[g] + g_C.mix[1] * sq3[g] + g_C.mix[2] * sq6;
      }
      float mg = fmaxf(gl[0], fmaxf(gl[1], gl[2]));
      float eg0 = __expf(gl[0] - mg), eg1 = __expf(gl[1] - mg), eg2 = __expf(gl[2] - mg);
      float ig = 1.0f / (eg0 + eg1 + eg2);

      int row = tile * TILE + wid;
      out[HEX_OFF + (size_t)row * 64 + lane] = hw0;
      out[HEX_OFF + (size_t)row * 64 + lane + 32] = hw1;
      hxa0 += hw0;
      hxa1 += hw1;
      if (lane == 0) {
        float g0 = eg0 * ig, g1 = eg1 * ig, g2 = eg2 * ig;
        out[(size_t)row * 3 + 0] = g0;
        out[(size_t)row * 3 + 1] = g1;
        out[(size_t)row * 3 + 2] = g2;
        ga0 += g0; ga1 += g1; ga2 += g2;
      }
    }
    __syncthreads();
  }

  // ---- per-block combine of lb accumulators ----
  comb[wid * 64 + lane] = hxa0;
  comb[wid * 64 + lane + 32] = hxa1;
  if (lane == 0) {
    combg[wid * 3 + 0] = ga0;
    combg[wid * 3 + 1] = ga1;
    combg[wid * 3 + 2] = ga2;
  }
  __syncthreads();
  if (t < 64) {
    float s = 0.f;
#pragma unroll
    for (int w = 0; w < 8; w++) s += comb[w * 64 + t];
    g_ph[blockIdx.x * 64 + t] = s;
  }
  if (t < 3) {
    float s = 0.f;
#pragma unroll
    for (int w = 0; w < 8; w++) s += combg[w * 3 + t];
    g_pg[blockIdx.x * 3 + t] = s;
  }

  // ---- fused final reduction: last block computes lb_loss ----
  __shared__ unsigned is_last;
  __threadfence();
  if (t == 0) {
    unsigned v = atomicAdd(&g_ctr, 1u);
    is_last = (v == GRID - 1) ? 1u : 0u;
  }
  __syncthreads();
  if (is_last) {
    int c = t & 63, st = t >> 6;  // 148 = 4 * 37
    const float* base = g_ph + (size_t)(st * 37) * 64 + c;
    float s = 0.f;
    for (int b = 0; b < 37; b++) s += base[b * 64];
    comb[st * 64 + c] = s;
    __syncthreads();
    if (t < 64) {
      float mh = (comb[t] + comb[64 + t] + comb[128 + t] + comb[192 + t]) *
                 (1.0f / (float)NROWS);
      p2[t] = 0.1f * mh * logf(mh + 1e-8f);
    } else if (t < 67) {
      int g = t - 64;
      float sg = 0.f;
      for (int b = 0; b < GRID; b++) sg += g_pg[b * 3 + g];
      float mg = sg * (1.0f / (float)NROWS);
      p2[t] = mg * logf(mg + 1e-8f);
    }
    __syncthreads();
    if (t == 0) {
      float lb = 0.f;
      for (int i = 0; i < 67; i++) lb += p2[i];
      out[LB_OFF] = lb;
      g_ctr = 0;  // reset for next graph replay
    }
  }
}

extern "C" void kernel_launch(void* const* d_in, const int* in_sizes, int n_in,
                              void* d_out, int out_size) {
  const float* x   = (const float*)d_in[0];
  const float* lnw = (const float*)d_in[1];
  const float* lnb = (const float*)d_in[2];
  const float* wq2 = (const float*)d_in[3];
  const float* wq3 = (const float*)d_in[4];
  const float* wq6 = (const float*)d_in[5];
  const float* lt  = (const float*)d_in[6];
  const float* lsm = (const float*)d_in[7];
  const float* q3g = (const float*)d_in[8];
  const float* lwm = (const float*)d_in[9];
  float* out = (float*)d_out;

  cudaFuncSetAttribute(main_kernel, cudaFuncAttributeMaxDynamicSharedMemorySize,
                       SMEM_BYTES);
  prep_kernel<<<12, 256>>>(lnw, lnb, wq2, wq3, wq6, lt, lsm, q3g, lwm);
  main_kernel<<<GRID, THREADS, SMEM_BYTES>>>(x, lnw, wq2, wq3, wq6, out);
}